// round 11
// baseline (speedup 1.0000x reference)
#include <cuda_runtime.h>
#include <cuda_fp16.h>

#define D 64
#define ALPHA 0.2f
#define MAX_N 131072
#define MAX_E 2200000
#define SCAN_B 512

// Static scratch (BSS zero-init; k_scan_apply re-zeroes g_cnt every run so
// graph replays always see a clean histogram).
__device__ int     g_cnt[MAX_N];
__device__ int     g_rowptr[MAX_N + 1];
__device__ int     g_blocksum[SCAN_B];
__device__ int     g_slot[MAX_E];     // per-edge within-row slot from hist
__device__ __align__(16) int g_colr[MAX_E];  // CSR-ordered column indices
__device__ float2  g_s1[MAX_N];       // per-node source-side scores (h0,h1)
__device__ float2  g_s2[MAX_N];       // per-node dest-side scores (h0,h1)
__device__ __half2 g_xh[MAX_N * 32];  // fp16 copy of x, 2 feats per lane

// Fused: blocks [0,nbE) do the edge histogram (slot assignment); blocks
// [nbE, nbE+nbW) do per-node score precompute + fp16 conversion of x.
__global__ void k_pre_hist(const float* __restrict__ x,
                           const float* __restrict__ W,
                           const float* __restrict__ a,
                           const int* __restrict__ row,
                           int n, int E, int nbE) {
    int t = threadIdx.x;
    if ((int)blockIdx.x < nbE) {
        int i = blockIdx.x * blockDim.x + t;
        if (i < E) g_slot[i] = atomicAdd(&g_cnt[row[i]], 1);
        return;
    }
    __shared__ float v00[64], v01[64], v10[64], v11[64]; // W[h][j]*a[h][..j]
    if (t < 64) {
        float w0 = W[t], w1 = W[64 + t];
        v00[t] = w0 * a[t];
        v01[t] = w0 * a[64 + t];
        v10[t] = w1 * a[128 + t];
        v11[t] = w1 * a[192 + t];
    }
    __syncthreads();
    int b = blockIdx.x - nbE;
    int warp = (b * blockDim.x + t) >> 5;
    int lane = t & 31;
    if (warp >= n) return;
    float2 xv = reinterpret_cast<const float2*>(x)[warp * 32 + lane];
    g_xh[warp * 32 + lane] = __floats2half2_rn(xv.x, xv.y);
    int l2 = lane * 2;
    float s10 = xv.x * v00[l2] + xv.y * v00[l2 + 1];
    float s20 = xv.x * v01[l2] + xv.y * v01[l2 + 1];
    float s11 = xv.x * v10[l2] + xv.y * v10[l2 + 1];
    float s21 = xv.x * v11[l2] + xv.y * v11[l2 + 1];
    #pragma unroll
    for (int o = 16; o; o >>= 1) {
        s10 += __shfl_xor_sync(0xffffffffu, s10, o);
        s20 += __shfl_xor_sync(0xffffffffu, s20, o);
        s11 += __shfl_xor_sync(0xffffffffu, s11, o);
        s21 += __shfl_xor_sync(0xffffffffu, s21, o);
    }
    if (lane == 0) {
        g_s1[warp] = make_float2(s10, s11);
        g_s2[warp] = make_float2(s20, s21);
    }
}

// Block-local exclusive scan of g_cnt -> g_rowptr (local) + block totals.
__global__ void k_scan1(int n) {
    __shared__ int sh[SCAN_B];
    int t = threadIdx.x;
    int i = blockIdx.x * SCAN_B + t;
    int v = (i < n) ? g_cnt[i] : 0;
    sh[t] = v;
    __syncthreads();
    #pragma unroll
    for (int o = 1; o < SCAN_B; o <<= 1) {
        int tmp = (t >= o) ? sh[t - o] : 0;
        __syncthreads();
        sh[t] += tmp;
        __syncthreads();
    }
    if (i < n) g_rowptr[i] = sh[t] - v;
    if (t == SCAN_B - 1) g_blocksum[blockIdx.x] = sh[t];
}

// Every block redundantly scans the (<=512) block sums in smem, adds its own
// base to the local prefixes, re-zeroes g_cnt, and caps rowptr[n]=E.
__global__ void k_scan_apply(int n, int E, int nb) {
    __shared__ int sh[SCAN_B];
    int t = threadIdx.x;
    sh[t] = (t < nb) ? g_blocksum[t] : 0;
    __syncthreads();
    #pragma unroll
    for (int o = 1; o < SCAN_B; o <<= 1) {
        int tmp = (t >= o) ? sh[t - o] : 0;
        __syncthreads();
        sh[t] += tmp;
        __syncthreads();
    }
    int base = (blockIdx.x == 0) ? 0 : sh[blockIdx.x - 1];
    int i = blockIdx.x * SCAN_B + t;
    if (i < n) {
        g_rowptr[i] += base;
        g_cnt[i] = 0;
    }
    if (i == n) g_rowptr[n] = E;
}

// Edge-parallel CSR fill — pure permutation now: one rowptr gather + one 4B
// scattered write per edge. No score gathers, no exp.
__global__ void k_scatter(const int* __restrict__ row,
                          const int* __restrict__ col, int E) {
    int i = blockIdx.x * blockDim.x + threadIdx.x;
    if (i >= E) return;
    g_colr[g_rowptr[row[i]] + g_slot[i]] = col[i];
}

// One warp per node. Weights computed here: s1 is the warp's own node (one
// load), s2[c] is a broadcast sector issued in parallel with the x gather.
// Cols consumed 4 per LDG.128 -> 4 independent s2 loads + 4 gathers in flight.
__global__ void k_aggregate(float* __restrict__ out, int n) {
    int warp = (blockIdx.x * blockDim.x + threadIdx.x) >> 5;
    int lane = threadIdx.x & 31;
    if (warp >= n) return;
    int beg = g_rowptr[warp];
    int end = g_rowptr[warp + 1];
    float2 s1 = g_s1[warp];
    float a00 = 0.f, a01 = 0.f, a10 = 0.f, a11 = 0.f;
    float rs0 = 0.f, rs1 = 0.f;

    int e = beg;
    // head: align e to 4 (16B boundary of g_colr)
    for (; e < end && (e & 3); e++) {
        int c = g_colr[e];
        float2 s2 = g_s2[c];
        float sc0 = s1.x + s2.x, sc1 = s1.y + s2.y;
        float w0 = __expf(sc0 > 0.f ? sc0 : ALPHA * sc0);
        float w1 = __expf(sc1 > 0.f ? sc1 : ALPHA * sc1);
        float2 xf = __half22float2(g_xh[c * 32 + lane]);
        a00 += w0 * xf.x; a01 += w0 * xf.y;
        a10 += w1 * xf.x; a11 += w1 * xf.y;
        rs0 += w0; rs1 += w1;
    }
    // main: 4 edges per aligned LDG.128 of column indices
    for (; e + 3 < end; e += 4) {
        int4 q = *reinterpret_cast<const int4*>(&g_colr[e]);
        float2 s2a = g_s2[q.x];
        float2 s2b = g_s2[q.y];
        float2 s2c = g_s2[q.z];
        float2 s2d = g_s2[q.w];
        float2 x0 = __half22float2(g_xh[q.x * 32 + lane]);
        float2 x1 = __half22float2(g_xh[q.y * 32 + lane]);
        float2 x2 = __half22float2(g_xh[q.z * 32 + lane]);
        float2 x3 = __half22float2(g_xh[q.w * 32 + lane]);
        float t0 = s1.x + s2a.x, u0 = s1.y + s2a.y;
        float t1 = s1.x + s2b.x, u1 = s1.y + s2b.y;
        float t2 = s1.x + s2c.x, u2 = s1.y + s2c.y;
        float t3 = s1.x + s2d.x, u3 = s1.y + s2d.y;
        float w00 = __expf(t0 > 0.f ? t0 : ALPHA * t0);
        float w10 = __expf(u0 > 0.f ? u0 : ALPHA * u0);
        float w01 = __expf(t1 > 0.f ? t1 : ALPHA * t1);
        float w11 = __expf(u1 > 0.f ? u1 : ALPHA * u1);
        float w02 = __expf(t2 > 0.f ? t2 : ALPHA * t2);
        float w12 = __expf(u2 > 0.f ? u2 : ALPHA * u2);
        float w03 = __expf(t3 > 0.f ? t3 : ALPHA * t3);
        float w13 = __expf(u3 > 0.f ? u3 : ALPHA * u3);
        a00 += w00 * x0.x; a01 += w00 * x0.y;
        a10 += w10 * x0.x; a11 += w10 * x0.y;
        rs0 += w00; rs1 += w10;
        a00 += w01 * x1.x; a01 += w01 * x1.y;
        a10 += w11 * x1.x; a11 += w11 * x1.y;
        rs0 += w01; rs1 += w11;
        a00 += w02 * x2.x; a01 += w02 * x2.y;
        a10 += w12 * x2.x; a11 += w12 * x2.y;
        rs0 += w02; rs1 += w12;
        a00 += w03 * x3.x; a01 += w03 * x3.y;
        a10 += w13 * x3.x; a11 += w13 * x3.y;
        rs0 += w03; rs1 += w13;
    }
    // tail
    for (; e < end; e++) {
        int c = g_colr[e];
        float2 s2 = g_s2[c];
        float sc0 = s1.x + s2.x, sc1 = s1.y + s2.y;
        float w0 = __expf(sc0 > 0.f ? sc0 : ALPHA * sc0);
        float w1 = __expf(sc1 > 0.f ? sc1 : ALPHA * sc1);
        float2 xf = __half22float2(g_xh[c * 32 + lane]);
        a00 += w0 * xf.x; a01 += w0 * xf.y;
        a10 += w1 * xf.x; a11 += w1 * xf.y;
        rs0 += w0; rs1 += w1;
    }

    float i0 = 0.5f / rs0, i1 = 0.5f / rs1;
    float2 o;
    o.x = a00 * i0 + a10 * i1;
    o.y = a01 * i0 + a11 * i1;
    reinterpret_cast<float2*>(out)[warp * 32 + lane] = o;
}

extern "C" void kernel_launch(void* const* d_in, const int* in_sizes, int n_in,
                              void* d_out, int out_size) {
    const float* x  = (const float*)d_in[0];
    const int*   ei = (const int*)d_in[1];
    const float* W  = (const float*)d_in[2];
    const float* a  = (const float*)d_in[3];
    float* out = (float*)d_out;

    int n = in_sizes[0] / D;
    int E = in_sizes[1] / 2;
    const int* row = ei;
    const int* col = ei + E;

    const int T = 256;
    int nbE = (E + T - 1) / T;
    int nbW = (n * 32 + T - 1) / T;          // one warp per node
    int nbS = (n + SCAN_B - 1) / SCAN_B;     // must be <= SCAN_B

    k_pre_hist<<<nbE + nbW, T>>>(x, W, a, row, n, E, nbE);
    k_scan1<<<nbS, SCAN_B>>>(n);
    k_scan_apply<<<(n + SCAN_B) / SCAN_B, SCAN_B>>>(n, E, nbS);
    k_scatter<<<nbE, T>>>(row, col, E);
    k_aggregate<<<nbW, T>>>(out, n);
}

// round 12
// speedup vs baseline: 1.0551x; 1.0551x over previous
#include <cuda_runtime.h>
#include <cuda_fp16.h>

#define D 64
#define ALPHA 0.2f
#define MAX_N 131072
#define MAX_E 2200000
#define SCAN_B 512

// Static scratch (BSS zero-init). Replay invariants: k_aggregate reads+zeros
// g_cnt; k_pre_hist zeroes g_total (separate launch, so ordering is safe).
__device__ int     g_cnt[MAX_N];
__device__ int     g_rowptr[MAX_N];
__device__ int     g_total;
__device__ int     g_slot[MAX_E];     // per-edge within-row slot from hist
__device__ __align__(16) unsigned long long g_rec[MAX_E]; // (col<<32)|half2(w0,w1)
__device__ float2  g_s1[MAX_N];       // per-node source-side scores (h0,h1)
__device__ float2  g_s2[MAX_N];       // per-node dest-side scores (h0,h1)
__device__ __half2 g_xh[MAX_N * 32];  // fp16 copy of x, 2 feats per lane

// Fused: blocks [0,nbE) do the edge histogram (slot assignment); blocks
// [nbE, nbE+nbW) do per-node score precompute + fp16 conversion of x.
__global__ void k_pre_hist(const float* __restrict__ x,
                           const float* __restrict__ W,
                           const float* __restrict__ a,
                           const int* __restrict__ row,
                           int n, int E, int nbE) {
    int t = threadIdx.x;
    if ((int)blockIdx.x < nbE) {
        if (blockIdx.x == 0 && t == 0) g_total = 0;   // replay reset
        int i = blockIdx.x * blockDim.x + t;
        if (i < E) g_slot[i] = atomicAdd(&g_cnt[row[i]], 1);
        return;
    }
    __shared__ float v00[64], v01[64], v10[64], v11[64]; // W[h][j]*a[h][..j]
    if (t < 64) {
        float w0 = W[t], w1 = W[64 + t];
        v00[t] = w0 * a[t];
        v01[t] = w0 * a[64 + t];
        v10[t] = w1 * a[128 + t];
        v11[t] = w1 * a[192 + t];
    }
    __syncthreads();
    int b = blockIdx.x - nbE;
    int warp = (b * blockDim.x + t) >> 5;
    int lane = t & 31;
    if (warp >= n) return;
    float2 xv = reinterpret_cast<const float2*>(x)[warp * 32 + lane];
    g_xh[warp * 32 + lane] = __floats2half2_rn(xv.x, xv.y);
    int l2 = lane * 2;
    float s10 = xv.x * v00[l2] + xv.y * v00[l2 + 1];
    float s20 = xv.x * v01[l2] + xv.y * v01[l2 + 1];
    float s11 = xv.x * v10[l2] + xv.y * v10[l2 + 1];
    float s21 = xv.x * v11[l2] + xv.y * v11[l2 + 1];
    // 6-SHFL multi-value butterfly (packs 4 reductions into one lane-sliced one)
    float u0 = (lane < 16 ? s10 : s20)
             + __shfl_xor_sync(0xffffffffu, (lane < 16 ? s20 : s10), 16);
    float u1 = (lane < 16 ? s11 : s21)
             + __shfl_xor_sync(0xffffffffu, (lane < 16 ? s21 : s11), 16);
    float v = ((lane & 8) ? u1 : u0)
            + __shfl_xor_sync(0xffffffffu, ((lane & 8) ? u0 : u1), 8);
    v += __shfl_xor_sync(0xffffffffu, v, 4);
    v += __shfl_xor_sync(0xffffffffu, v, 2);
    v += __shfl_xor_sync(0xffffffffu, v, 1);
    // v: s10 @ lane0, s11 @ lane8, s20 @ lane16, s21 @ lane24
    if (lane == 0)  g_s1[warp].x = v;
    if (lane == 8)  g_s1[warp].y = v;
    if (lane == 16) g_s2[warp].x = v;
    if (lane == 24) g_s2[warp].y = v;
}

// Single-pass scan: block-local exclusive scan of g_cnt; the block claims its
// base range with one atomicAdd on g_total. Row ranges are disjoint (all that
// scatter/aggregate need) though not globally ordered. g_cnt is kept (it is
// the per-node degree for aggregate, which resets it afterward).
__global__ void k_scan(int n) {
    __shared__ int sh[SCAN_B];
    __shared__ int base_sh;
    int t = threadIdx.x;
    int i = blockIdx.x * SCAN_B + t;
    int vv = (i < n) ? g_cnt[i] : 0;
    sh[t] = vv;
    __syncthreads();
    #pragma unroll
    for (int o = 1; o < SCAN_B; o <<= 1) {
        int tmp = (t >= o) ? sh[t - o] : 0;
        __syncthreads();
        sh[t] += tmp;
        __syncthreads();
    }
    if (t == SCAN_B - 1) base_sh = atomicAdd(&g_total, sh[t]);
    __syncthreads();
    if (i < n) g_rowptr[i] = base_sh + sh[t] - vv;
}

// Edge-parallel CSR fill (atomic-free): both head weights in fp16, packed
// with the column index into one 8-byte record.
__global__ void k_scatter(const int* __restrict__ row,
                          const int* __restrict__ col, int E) {
    int i = blockIdx.x * blockDim.x + threadIdx.x;
    if (i >= E) return;
    int r = row[i], c = col[i];
    int pos = g_rowptr[r] + g_slot[i];
    float2 s1 = g_s1[r];
    float2 s2 = g_s2[c];
    float sc0 = s1.x + s2.x;
    float sc1 = s1.y + s2.y;
    float w0 = __expf(sc0 > 0.f ? sc0 : ALPHA * sc0);
    float w1 = __expf(sc1 > 0.f ? sc1 : ALPHA * sc1);
    __half2 wh = __floats2half2_rn(w0, w1);
    unsigned wbits = *reinterpret_cast<unsigned*>(&wh);
    g_rec[pos] = ((unsigned long long)(unsigned)c << 32) | wbits;
}

// One warp per node. Records consumed in aligned pairs (one LDG.128 covers
// two edges; the two gathers are independent -> MLP 2 on the L2-resident x).
// deg comes from g_cnt (reset here for the next graph replay).
__global__ void k_aggregate(float* __restrict__ out, int n) {
    int warp = (blockIdx.x * blockDim.x + threadIdx.x) >> 5;
    int lane = threadIdx.x & 31;
    if (warp >= n) return;
    int beg = g_rowptr[warp];
    int deg = g_cnt[warp];
    if (lane == 0) g_cnt[warp] = 0;
    int end = beg + deg;
    float a00 = 0.f, a01 = 0.f, a10 = 0.f, a11 = 0.f;
    float rs0 = 0.f, rs1 = 0.f;

    int e = beg;
    if (e < end && (e & 1)) {          // head: align to even index
        unsigned long long r = g_rec[e];
        unsigned lo = (unsigned)r;
        int c = (int)(r >> 32);
        float2 w = __half22float2(*reinterpret_cast<__half2*>(&lo));
        float2 xf = __half22float2(g_xh[c * 32 + lane]);
        a00 += w.x * xf.x; a01 += w.x * xf.y;
        a10 += w.y * xf.x; a11 += w.y * xf.y;
        rs0 += w.x; rs1 += w.y;
        e++;
    }
    for (; e + 1 < end; e += 2) {      // aligned pair
        uint4 q = *reinterpret_cast<const uint4*>(&g_rec[e]);
        int c0 = (int)q.y, c1 = (int)q.w;
        float2 w0 = __half22float2(*reinterpret_cast<__half2*>(&q.x));
        float2 w1 = __half22float2(*reinterpret_cast<__half2*>(&q.z));
        float2 x0 = __half22float2(g_xh[c0 * 32 + lane]);
        float2 x1 = __half22float2(g_xh[c1 * 32 + lane]);
        a00 += w0.x * x0.x; a01 += w0.x * x0.y;
        a10 += w0.y * x0.x; a11 += w0.y * x0.y;
        rs0 += w0.x; rs1 += w0.y;
        a00 += w1.x * x1.x; a01 += w1.x * x1.y;
        a10 += w1.y * x1.x; a11 += w1.y * x1.y;
        rs0 += w1.x; rs1 += w1.y;
    }
    if (e < end) {                     // tail
        unsigned long long r = g_rec[e];
        unsigned lo = (unsigned)r;
        int c = (int)(r >> 32);
        float2 w = __half22float2(*reinterpret_cast<__half2*>(&lo));
        float2 xf = __half22float2(g_xh[c * 32 + lane]);
        a00 += w.x * xf.x; a01 += w.x * xf.y;
        a10 += w.y * xf.x; a11 += w.y * xf.y;
        rs0 += w.x; rs1 += w.y;
    }

    float i0 = 0.5f / rs0, i1 = 0.5f / rs1;
    float2 o;
    o.x = a00 * i0 + a10 * i1;
    o.y = a01 * i0 + a11 * i1;
    reinterpret_cast<float2*>(out)[warp * 32 + lane] = o;
}

extern "C" void kernel_launch(void* const* d_in, const int* in_sizes, int n_in,
                              void* d_out, int out_size) {
    const float* x  = (const float*)d_in[0];
    const int*   ei = (const int*)d_in[1];
    const float* W  = (const float*)d_in[2];
    const float* a  = (const float*)d_in[3];
    float* out = (float*)d_out;

    int n = in_sizes[0] / D;
    int E = in_sizes[1] / 2;
    const int* row = ei;
    const int* col = ei + E;

    const int T = 256;
    int nbE = (E + T - 1) / T;
    int nbW = (n * 32 + T - 1) / T;          // one warp per node
    int nbS = (n + SCAN_B - 1) / SCAN_B;

    k_pre_hist<<<nbE + nbW, T>>>(x, W, a, row, n, E, nbE);
    k_scan<<<nbS, SCAN_B>>>(n);
    k_scatter<<<nbE, T>>>(row, col, E);
    k_aggregate<<<nbW, T>>>(out, n);
}